// round 6
// baseline (speedup 1.0000x reference)
#include <cuda_runtime.h>
#include <cuda_bf16.h>
#include <math.h>
#include <stdint.h>

#define NTOK 13320
#define BATCH 240
#define DM 512
#define DI 2048
#define NH 8
#define DKH 64
#define LNEPS 1e-5f
#define NQ 1024
#define NKV 2048

typedef unsigned long long u64;

// ================= scratch (static device globals; no allocation) =================
__device__ float g_Q4 [2 * NTOK * NQ];          // [src][row][half*512+col]
__device__ float g_KV4[2 * NTOK * NKV];         // [src][row][half*1024 + (K|V)*512 + col]
__device__ float g_t14  [4 * NTOK * DM];
__device__ float g_out14[4 * NTOK * DM];
__device__ int   g_offs[BATCH + 1];
__device__ float g_bq4 [2 * NQ];
__device__ float g_bkv4[2 * NKV];

__device__ __nv_bfloat16 g_visb  [NTOK * DM];
__device__ __nv_bfloat16 g_txtb  [NTOK * DM];
__device__ __nv_bfloat16 g_ctxb4 [4 * NTOK * DM];
__device__ __nv_bfloat16 g_out1b4[4 * NTOK * DM];
__device__ __nv_bfloat16 g_hb4   [4 * NTOK * DI];

__device__ __nv_bfloat16 g_WqT4 [2 * NQ * DM];
__device__ __nv_bfloat16 g_WkvT4[2 * NKV * DM];
__device__ __nv_bfloat16 g_WoT  [4 * DM * DM];
__device__ __nv_bfloat16 g_W1T  [4 * DI * DM];
__device__ __nv_bfloat16 g_W2T  [4 * DM * DI];

// ================= helpers =================
__device__ __forceinline__ uint32_t smem_u32(const void* p) {
    uint32_t a;
    asm("{ .reg .u64 t; cvta.to.shared.u64 t, %1; cvt.u32.u64 %0, t; }" : "=r"(a) : "l"(p));
    return a;
}
__device__ __forceinline__ void cp_async16(uint32_t dst, const void* src) {
    asm volatile("cp.async.cg.shared.global [%0], [%1], 16;" :: "r"(dst), "l"(src));
}
#define CP_COMMIT() asm volatile("cp.async.commit_group;" ::: "memory")
#define CP_WAIT(n)  asm volatile("cp.async.wait_group %0;" :: "n"(n) : "memory")

__device__ __forceinline__ void ldmatrix_x4(uint32_t& r0, uint32_t& r1, uint32_t& r2, uint32_t& r3, uint32_t addr) {
    asm volatile("ldmatrix.sync.aligned.m8n8.x4.shared.b16 {%0,%1,%2,%3}, [%4];"
        : "=r"(r0), "=r"(r1), "=r"(r2), "=r"(r3) : "r"(addr));
}
__device__ __forceinline__ void mma_bf16(float* d, const uint32_t* a, const uint32_t* b) {
    asm volatile("mma.sync.aligned.m16n8k16.row.col.f32.bf16.bf16.f32 "
        "{%0,%1,%2,%3}, {%4,%5,%6,%7}, {%8,%9}, {%0,%1,%2,%3};"
        : "+f"(d[0]), "+f"(d[1]), "+f"(d[2]), "+f"(d[3])
        : "r"(a[0]), "r"(a[1]), "r"(a[2]), "r"(a[3]), "r"(b[0]), "r"(b[1]));
}
__device__ __forceinline__ u64 q_at(const ulong4& q, int z) {
    u64 v;
    switch (z) { case 0: v = q.x; break; case 1: v = q.y; break;
                 case 2: v = q.z; break; default: v = q.w; }
    return v;
}

// ================= prepass kernels =================
__global__ void offsets_kernel(const int* __restrict__ num_objs) {
    if (threadIdx.x == 0) {
        int s = 0;
        for (int i = 0; i < BATCH; i++) { g_offs[i] = s; s += num_objs[i]; }
        g_offs[BATCH] = s;
    }
}

__global__ void bias_concat_kernel(const float* __restrict__ bq, const float* __restrict__ bk,
                                   const float* __restrict__ bv) {
    int i = blockIdx.x * blockDim.x + threadIdx.x;     // 0..6143
    if (i < 2 * NQ) {
        int src = i >> 10, half = (i >> 9) & 1, j = i & 511;
        int p = src + 2 * half;
        g_bq4[i] = bq[p * DM + j];
    } else if (i < 2 * NQ + 2 * NKV) {
        int k = i - 2 * NQ;
        int src = k >> 11, r = k & 2047;
        int half = r >> 10, part = (r >> 9) & 1, j = r & 511;
        const int pt[2][2] = { {0, 3}, {2, 1} };
        int p = pt[src][half];
        g_bkv4[k] = (part ? bv : bk)[p * DM + j];
    }
}

// fused bf16 convert for vis+txt
__global__ __launch_bounds__(256) void cvt_bf16_kernel(const float* __restrict__ V,
                                                       const float* __restrict__ T, int n4) {
    int i = blockIdx.x * blockDim.x + threadIdx.x;
    const float* X; __nv_bfloat16* Y; int j;
    if (i < n4) { X = V; Y = g_visb; j = i; }
    else if (i < 2 * n4) { X = T; Y = g_txtb; j = i - n4; }
    else return;
    float4 v = ((const float4*)X)[j];
    __nv_bfloat162 a, b;
    a.x = __float2bfloat16_rn(v.x); a.y = __float2bfloat16_rn(v.y);
    b.x = __float2bfloat16_rn(v.z); b.y = __float2bfloat16_rn(v.w);
    ((__nv_bfloat162*)Y)[j * 2 + 0] = a;
    ((__nv_bfloat162*)Y)[j * 2 + 1] = b;
}

// one-launch transpose of all 24 weight blocks (src fp32 [R x C] -> dst bf16 [C x R])
struct TT { u64 src[24]; u64 dst[24]; };
__global__ __launch_bounds__(256) void transpose_all_kernel(TT tt) {
    int bid = blockIdx.x;
    int e, t, R, C;
    if (bid < 4096)      { e = bid >> 8, t = bid & 255;  R = 512;  C = 512;  }
    else if (bid < 8192) { e = 16 + ((bid - 4096) >> 10); t = (bid - 4096) & 1023; R = 512;  C = 2048; }
    else                 { e = 20 + ((bid - 8192) >> 10); t = (bid - 8192) & 1023; R = 2048; C = 512;  }
    const float* Sp = (const float*)tt.src[e];
    __nv_bfloat16* Dp = (__nv_bfloat16*)tt.dst[e];
    int tpr = C >> 5;
    int bx = (t % tpr) * 32, by = (t / tpr) * 32;

    __shared__ float tile[32][33];
    int x = bx + threadIdx.x;
#pragma unroll
    for (int yy = threadIdx.y; yy < 32; yy += 8)
        tile[yy][threadIdx.x] = Sp[(size_t)(by + yy) * C + x];
    __syncthreads();
    int x2 = by + threadIdx.x;
#pragma unroll
    for (int yy = threadIdx.y; yy < 32; yy += 8)
        Dp[(size_t)(bx + yy) * R + x2] = __float2bfloat16_rn(tile[threadIdx.x][yy]);
}

// ======== bf16 mma.sync GEMM, 128x256 tile, z-batched ========
#define LDSH 40
#define A_TILEB (128 * LDSH * 2)           // 10240
#define B_TILEB (256 * LDSH * 2)           // 20480
#define STAGEB (A_TILEB + B_TILEB)         // 30720
#define NSTAGE 4
#define GEMM_SMEM (NSTAGE * STAGEB)        // 122880

template <bool RELU, bool RESID, bool OF32, bool OBF16>
__global__ __launch_bounds__(256) void gemm_bf16_k(
    ulong4 Aq, ulong4 Btq, ulong4 biasq, ulong4 Rq,
    float* __restrict__ C, size_t cStr, __nv_bfloat16* __restrict__ Cb, size_t cbStr,
    int M, int K, int N)
{
    extern __shared__ char smem[];
    const uint32_t sb = smem_u32(smem);
    const int tid = threadIdx.x;
    const int lane = tid & 31;
    const int wid = tid >> 5;
    const int z = blockIdx.z;
    const int m0 = blockIdx.y * 128;
    const int n0 = blockIdx.x * 256;
    const int warp_m = wid & 1;          // 2 -> 64-row bands
    const int warp_n = wid >> 1;         // 4 -> 64-col bands

    const __nv_bfloat16* A  = (const __nv_bfloat16*)q_at(Aq, z);
    const __nv_bfloat16* Bt = (const __nv_bfloat16*)q_at(Btq, z);
    const float* bias = (const float*)q_at(biasq, z);
    const float* R = RESID ? (const float*)q_at(Rq, z) : nullptr;
    if (OF32)  C  += (size_t)z * cStr;
    if (OBF16) Cb += (size_t)z * cbStr;

    float acc[4][8][4];
#pragma unroll
    for (int i = 0; i < 4; i++)
#pragma unroll
        for (int j = 0; j < 8; j++)
#pragma unroll
            for (int r = 0; r < 4; r++) acc[i][j][r] = 0.f;

    const int lmrow  = lane & 15;
    const int lmbyte = (lane >> 4) * 16;
    const int KT = K >> 5;

    auto load_stage = [&](int s, int kit) {
        const int k0 = kit << 5;
        const uint32_t base = sb + (uint32_t)s * STAGEB;
#pragma unroll
        for (int i = 0; i < 2; i++) {
            int c = tid + i * 256;            // 0..511
            int row = c >> 2, c16 = c & 3;
            int gr = m0 + row; gr = gr < M ? gr : M - 1;
            cp_async16(base + row * (LDSH * 2) + c16 * 16,
                       A + (size_t)gr * K + k0 + c16 * 8);
        }
#pragma unroll
        for (int i = 0; i < 4; i++) {
            int c = tid + i * 256;            // 0..1023
            int row = c >> 2, c16 = c & 3;
            cp_async16(base + A_TILEB + row * (LDSH * 2) + c16 * 16,
                       Bt + (size_t)(n0 + row) * K + k0 + c16 * 8);
        }
        CP_COMMIT();
    };

#pragma unroll
    for (int s = 0; s < NSTAGE - 1; s++) load_stage(s, s);

#pragma unroll 1
    for (int it = 0; it < KT; it++) {
        CP_WAIT(NSTAGE - 2);
        __syncthreads();                      // all warps done with iter it-1
        int nk = it + NSTAGE - 1;
        if (nk < KT) load_stage(nk % NSTAGE, nk);   // safe: overwrites stage read in it-1
        else CP_COMMIT();

        const uint32_t ab = sb + (uint32_t)(it % NSTAGE) * STAGEB;
        const uint32_t bb = ab + A_TILEB;

#pragma unroll
        for (int kk = 0; kk < 2; kk++) {
            uint32_t af[4][4];
#pragma unroll
            for (int mi = 0; mi < 4; mi++) {
                uint32_t addr = ab + (warp_m * 64 + mi * 16 + lmrow) * (LDSH * 2) + kk * 32 + lmbyte;
                ldmatrix_x4(af[mi][0], af[mi][1], af[mi][2], af[mi][3], addr);
            }
            uint32_t bf[8][2];
#pragma unroll
            for (int t = 0; t < 4; t++) {
                uint32_t addr = bb + (warp_n * 64 + t * 16 + lmrow) * (LDSH * 2) + kk * 32 + lmbyte;
                uint32_t r0, r1, r2, r3;
                ldmatrix_x4(r0, r1, r2, r3, addr);
                bf[t * 2 + 0][0] = r0; bf[t * 2 + 0][1] = r2;
                bf[t * 2 + 1][0] = r1; bf[t * 2 + 1][1] = r3;
            }
#pragma unroll
            for (int mi = 0; mi < 4; mi++)
#pragma unroll
                for (int nj = 0; nj < 8; nj++)
                    mma_bf16(acc[mi][nj], af[mi], bf[nj]);
        }
    }

    const int er = lane >> 2;
    const int ec = (lane & 3) * 2;
#pragma unroll
    for (int mi = 0; mi < 4; mi++) {
#pragma unroll
        for (int half = 0; half < 2; half++) {
            int row = m0 + warp_m * 64 + mi * 16 + half * 8 + er;
            if (row >= M) continue;
#pragma unroll
            for (int nj = 0; nj < 8; nj++) {
                int col = n0 + warp_n * 64 + nj * 8 + ec;
                float2 v;
                v.x = acc[mi][nj][half * 2 + 0] + bias[col + 0];
                v.y = acc[mi][nj][half * 2 + 1] + bias[col + 1];
                if (RESID) {
                    const float2 rv = *(const float2*)(R + (size_t)row * N + col);
                    v.x += rv.x; v.y += rv.y;
                }
                if (RELU) { v.x = fmaxf(v.x, 0.f); v.y = fmaxf(v.y, 0.f); }
                if (OF32)
                    *(float2*)(C + (size_t)row * N + col) = v;
                if (OBF16) {
                    __nv_bfloat162 h2;
                    h2.x = __float2bfloat16_rn(v.x);
                    h2.y = __float2bfloat16_rn(v.y);
                    *(__nv_bfloat162*)(Cb + (size_t)row * N + col) = h2;
                }
            }
        }
    }
}

// ================= LN1 (z-batched, f32 + bf16 out) =================
__global__ __launch_bounds__(128) void ln1_kernel(
    const float* __restrict__ X, size_t xStr, ulong4 gq, ulong4 bq,
    float* __restrict__ out, size_t oStr, __nv_bfloat16* __restrict__ outb, size_t obStr)
{
    int row = blockIdx.x;
    int e = blockIdx.y;
    int tid = threadIdx.x;
    X += (size_t)e * xStr;
    out += (size_t)e * oStr;
    const float* g = (const float*)q_at(gq, e);
    const float* b = (const float*)q_at(bq, e);

    float4 v = ((const float4*)(X + (size_t)row * DM))[tid];
    __shared__ float sbuf[8];
    int wid = tid >> 5, lane = tid & 31;

    float s = v.x + v.y + v.z + v.w;
#pragma unroll
    for (int o = 16; o > 0; o >>= 1) s += __shfl_xor_sync(0xffffffffu, s, o);
    if (lane == 0) sbuf[wid] = s;
    __syncthreads();
    float mean = (sbuf[0] + sbuf[1] + sbuf[2] + sbuf[3]) * (1.0f / DM);
    __syncthreads();

    float dx0 = v.x - mean, dx1 = v.y - mean, dx2 = v.z - mean, dx3 = v.w - mean;
    float sq = dx0 * dx0 + dx1 * dx1 + dx2 * dx2 + dx3 * dx3;
#pragma unroll
    for (int o = 16; o > 0; o >>= 1) sq += __shfl_xor_sync(0xffffffffu, sq, o);
    if (lane == 0) sbuf[wid] = sq;
    __syncthreads();
    float var = (sbuf[0] + sbuf[1] + sbuf[2] + sbuf[3]) * (1.0f / DM);
    float rstd = rsqrtf(var + LNEPS);

    float4 gg = ((const float4*)g)[tid];
    float4 bb = ((const float4*)b)[tid];
    float4 y;
    y.x = dx0 * rstd * gg.x + bb.x;
    y.y = dx1 * rstd * gg.y + bb.y;
    y.z = dx2 * rstd * gg.z + bb.z;
    y.w = dx3 * rstd * gg.w + bb.w;

    ((float4*)(out + (size_t)row * DM))[tid] = y;
    __nv_bfloat16* ob = outb + (size_t)e * obStr + (size_t)row * DM;
    __nv_bfloat162 a, c;
    a.x = __float2bfloat16_rn(y.x); a.y = __float2bfloat16_rn(y.y);
    c.x = __float2bfloat16_rn(y.z); c.y = __float2bfloat16_rn(y.w);
    ((__nv_bfloat162*)ob)[tid * 2 + 0] = a;
    ((__nv_bfloat162*)ob)[tid * 2 + 1] = c;
}

// ============ LN2 pair + sum: out[p] = LN(T14[2p]) + LN(T14[2p+1]) ============
__global__ __launch_bounds__(128) void ln2_pair_kernel(
    const float* __restrict__ X, size_t xStr, ulong4 gq, ulong4 bq, float* __restrict__ out)
{
    int row = blockIdx.x;
    int p = blockIdx.y;
    int tid = threadIdx.x;
    int wid = tid >> 5, lane = tid & 31;

    const float* X0 = X + (size_t)(2 * p) * xStr + (size_t)row * DM;
    const float* X1 = X + (size_t)(2 * p + 1) * xStr + (size_t)row * DM;
    float4 v0 = ((const float4*)X0)[tid];
    float4 v1 = ((const float4*)X1)[tid];

    __shared__ float sbuf[16];
    float s0 = v0.x + v0.y + v0.z + v0.w;
    float s1 = v1.x + v1.y + v1.z + v1.w;
#pragma unroll
    for (int o = 16; o > 0; o >>= 1) {
        s0 += __shfl_xor_sync(0xffffffffu, s0, o);
        s1 += __shfl_xor_sync(0xffffffffu, s1, o);
    }
    if (lane == 0) { sbuf[wid] = s0; sbuf[8 + wid] = s1; }
    __syncthreads();
    float mean0 = (sbuf[0] + sbuf[1] + sbuf[2] + sbuf[3]) * (1.0f / DM);
    float mean1 = (sbuf[8] + sbuf[9] + sbuf[10] + sbuf[11]) * (1.0f / DM);
    __syncthreads();

    float a0 = v0.x - mean0, a1 = v0.y - mean0, a2 = v0.z - mean0, a3 = v0.w - mean0;
    float c0 = v1.x - mean1, c1 = v1.y - mean1, c2 = v1.z - mean1, c3 = v1.w - mean1;
    float q0 = a0 * a0 + a1 * a1 + a2 * a2 + a3 * a3;
    float q1 = c0 * c0 + c1 * c1 + c2 * c2 + c3 * c3;
#pragma unroll
    for (int o = 16; o > 0; o >>= 1) {
        q0 += __shfl_xor_sync(0xffffffffu, q0, o);
        q1 += __shfl_xor_sync(0xffffffffu, q1, o);
    }
    if (lane == 0) { sbuf[wid] = q0; sbuf[8 + wid] = q1; }
    __syncthreads();
    float rstd0 = rsqrtf((sbuf[0] + sbuf[1] + sbuf[2] + sbuf[3]) * (1.0f / DM) + LNEPS);
    float rstd1 = rsqrtf((sbuf[8] + sbuf[9] + sbuf[10] + sbuf[11]) * (1.0f / DM) + LNEPS);

    const float* g0 = (const float*)q_at(gq, 2 * p);
    const float* b0 = (const float*)q_at(bq, 2 * p);
    const float* g1 = (const float*)q_at(gq, 2 * p + 1);
    const float* b1 = (const float*)q_at(bq, 2 * p + 1);
    float4 gg0 = ((const float4*)g0)[tid], bb0 = ((const float4*)b0)[tid];
    float4 gg1 = ((const float4*)g1)[tid], bb1 = ((const float4*)b1)[tid];

    float4 y;
    y.x = (a0 * rstd0 * gg0.x + bb0.x) + (c0 * rstd1 * gg1.x + bb1.x);
    y.y = (a1 * rstd0 * gg0.y + bb0.y) + (c1 * rstd1 * gg1.y + bb1.y);
    y.z = (a2 * rstd0 * gg0.z + bb0.z) + (c2 * rstd1 * gg1.z + bb1.z);
    y.w = (a3 * rstd0 * gg0.w + bb0.w) + (c3 * rstd1 * gg1.w + bb1.w);

    ((float4*)(out + (size_t)p * NTOK * DM + (size_t)row * DM))[tid] = y;
}

// ================= segment attention (all 4 encoders) =================
__global__ __launch_bounds__(96) void attn_kernel()
{
    int s = blockIdx.x;
    int h = blockIdx.y;
    int e = blockIdx.z;
    int off = g_offs[s];
    int L = g_offs[s + 1] - off;

    const int srcQ = e >> 1, halfQ = e & 1;
    const int srcKV_t[4]  = {0, 1, 1, 0};
    const int halfKV_t[4] = {0, 0, 1, 1};
    const int srcKV = srcKV_t[e], halfKV = halfKV_t[e];

    const float* Qbase = g_Q4  + (size_t)srcQ  * NTOK * NQ  + halfQ  * DM + h * DKH;
    const float* Kbase = g_KV4 + (size_t)srcKV * NTOK * NKV + halfKV * NQ + h * DKH;
    const float* Vbase = Kbase + DM;

    __shared__ float Ks[95 * DKH];
    __shared__ float Vs[95 * DKH];
    for (int idx = threadIdx.x; idx < L * 16; idx += 96) {
        int j = idx >> 4, d4 = idx & 15;
        ((float4*)Ks)[j * 16 + d4] = ((const float4*)(Kbase + (size_t)(off + j) * NKV))[d4];
        ((float4*)Vs)[j * 16 + d4] = ((const float4*)(Vbase + (size_t)(off + j) * NKV))[d4];
    }
    __syncthreads();

    int i = threadIdx.x;
    if (i >= L) return;

    float q[DKH];
    const float4* qp = (const float4*)(Qbase + (size_t)(off + i) * NQ);
#pragma unroll
    for (int t = 0; t < 16; t++) {
        float4 u = qp[t];
        q[4 * t + 0] = u.x; q[4 * t + 1] = u.y; q[4 * t + 2] = u.z; q[4 * t + 3] = u.w;
    }

    float m = -INFINITY, l = 0.f;
    float acc[DKH];
#pragma unroll
    for (int d = 0; d < DKH; d++) acc[d] = 0.f;

    for (int j0 = 0; j0 < L; j0 += 8) {
        int nj = L - j0; if (nj > 8) nj = 8;
        float sc[8];
#pragma unroll
        for (int jj = 0; jj < 8; jj++) {
            if (jj < nj) {
                const float4* kr = (const float4*)&Ks[(j0 + jj) * DKH];
                float sd = 0.f;
#pragma unroll
                for (int t = 0; t < 16; t++) {
                    float4 kv = kr[t];
                    sd = fmaf(q[4 * t + 0], kv.x, sd);
                    sd = fmaf(q[4 * t + 1], kv.y, sd);
                    sd = fmaf(q[4 * t + 2], kv.z, sd);
                    sd = fmaf(q[4 * t + 3], kv.w, sd);
                }
                sc[jj] = sd * 0.125f;
            } else sc[jj] = -INFINITY;
        }
        float cm = sc[0];
#pragma unroll
        for (int jj = 1; jj < 8; jj++) cm = fmaxf(cm, sc[jj]);
        float mn = fmaxf(m, cm);
        float corr = __expf(m - mn);
        l *= corr;
#pragma unroll
        for (int d = 0; d < DKH; d++) acc[d] *= corr;
#pragma unroll
        for (int jj = 0; jj < 8; jj++) {
            if (jj < nj) {
                float p = __expf(sc[jj] - mn);
                l += p;
                const float4* vr = (const float4*)&Vs[(j0 + jj) * DKH];
#pragma unroll
                for (int t = 0; t < 16; t++) {
                    float4 vv = vr[t];
                    acc[4 * t + 0] = fmaf(p, vv.x, acc[4 * t + 0]);
                    acc[4 * t + 1] = fmaf(p, vv.y, acc[4 * t + 1]);
                    acc[4 * t + 2] = fmaf(p, vv.z, acc[4 * t + 2]);
                    acc[4 * t + 3] = fmaf(p, vv.w, acc[4 * t + 3]);
                }
            }
        }
        m = mn;
    }

    float inv = 1.0f / l;
    __nv_bfloat162* o = (__nv_bfloat162*)(g_ctxb4 + (size_t)e * NTOK * DM + (size_t)(off + i) * DM + h * DKH);
#pragma unroll
    for (int t = 0; t < 32; t++) {
        __nv_bfloat162 h2;
        h2.x = __float2bfloat16_rn(acc[2 * t + 0] * inv);
        h2.y = __float2bfloat16_rn(acc[2 * t + 1] * inv);
        o[t] = h2;
    }
}

// ================= host =================
extern "C" void kernel_launch(void* const* d_in, const int* in_sizes, int n_in,
                              void* d_out, int out_size)
{
    const float* vis  = (const float*)d_in[0];
    const float* txt  = (const float*)d_in[1];
    const float* Wq   = (const float*)d_in[2];
    const float* bq   = (const float*)d_in[3];
    const float* Wk   = (const float*)d_in[4];
    const float* bk   = (const float*)d_in[5];
    const float* Wv   = (const float*)d_in[6];
    const float* bv   = (const float*)d_in[7];
    const float* Wo   = (const float*)d_in[8];
    const float* bo   = (const float*)d_in[9];
    const float* g1   = (const float*)d_in[10];
    const float* be1  = (const float*)d_in[11];
    const float* W1   = (const float*)d_in[12];
    const float* b1   = (const float*)d_in[13];
    const float* W2   = (const float*)d_in[14];
    const float* b2   = (const float*)d_in[15];
    const float* g2   = (const float*)d_in[16];
    const float* be2  = (const float*)d_in[17];
    const int*   nobj = (const int*)d_in[18];
    float* out = (float*)d_out;

    float *Q4, *KV4, *T14, *OUT14, *BQ4, *BKV4;
    __nv_bfloat16 *VISB, *TXTB, *CTXB4, *OUT1B4, *HB4;
    __nv_bfloat16 *WqT4, *WkvT4, *WoT, *W1T, *W2T;
    cudaGetSymbolAddress((void**)&Q4, g_Q4);
    cudaGetSymbolAddress((void**)&KV4, g_KV4);
    cudaGetSymbolAddress((void**)&T14, g_t14);
    cudaGetSymbolAddress((void**)&OUT14, g_out14);
    cudaGetSymbolAddress((void**)&BQ4, g_bq4);
    cudaGetSymbolAddress((void**)&BKV4, g_bkv4);
    cudaGetSymbolAddress((void**)&VISB, g_visb);
    cudaGetSymbolAddress((void**)&TXTB, g_txtb);
    cudaGetSymbolAddress((void**)&CTXB4, g_ctxb4);
    cudaGetSymbolAddress((void**)&OUT1B4, g_out1b4);
    cudaGetSymbolAddress((void**)&HB4, g_hb4);
    cudaGetSymbolAddress((void**)&WqT4, g_WqT4);
    cudaGetSymbolAddress((void**)&WkvT4, g_WkvT4);
    cudaGetSymbolAddress((void**)&WoT, g_WoT);
    cudaGetSymbolAddress((void**)&W1T, g_W1T);
    cudaGetSymbolAddress((void**)&W2T, g_W2T);

    cudaFuncSetAttribute(gemm_bf16_k<false, false, true,  false>, cudaFuncAttributeMaxDynamicSharedMemorySize, GEMM_SMEM);
    cudaFuncSetAttribute(gemm_bf16_k<false, true,  true,  false>, cudaFuncAttributeMaxDynamicSharedMemorySize, GEMM_SMEM);
    cudaFuncSetAttribute(gemm_bf16_k<true,  false, false, true >, cudaFuncAttributeMaxDynamicSharedMemorySize, GEMM_SMEM);

    auto U4 = [](const void* a, const void* b, const void* c, const void* d) {
        ulong4 u; u.x = (u64)a; u.y = (u64)b; u.z = (u64)c; u.w = (u64)d; return u;
    };

    offsets_kernel<<<1, 32>>>(nobj);
    bias_concat_kernel<<<24, 256>>>(bq, bk, bv);

    const int NC4 = NTOK * DM / 4;
    cvt_bf16_kernel<<<(2 * NC4 + 255) / 256, 256>>>(vis, txt, NC4);

    // single transpose launch for all 24 weight blocks
    {
        TT tt;
        const size_t BLK = (size_t)DM * DM;
        const u64 qoff[4] = {0, 2 * BLK, BLK, 3 * BLK};
        const u64 koff[4] = {0, 6 * BLK, 4 * BLK, 2 * BLK};
        const u64 voff[4] = {BLK, 7 * BLK, 5 * BLK, 3 * BLK};
        for (int p = 0; p < 4; p++) {
            tt.src[p]      = (u64)(Wq + (size_t)p * BLK); tt.dst[p]      = (u64)(WqT4 + qoff[p]);
            tt.src[4 + p]  = (u64)(Wk + (size_t)p * BLK); tt.dst[4 + p]  = (u64)(WkvT4 + koff[p]);
            tt.src[8 + p]  = (u64)(Wv + (size_t)p * BLK); tt.dst[8 + p]  = (u64)(WkvT4 + voff[p]);
            tt.src[12 + p] = (u64)(Wo + (size_t)p * BLK); tt.dst[12 + p] = (u64)(WoT + (size_t)p * BLK);
            tt.src[16 + p] = (u64)(W1 + (size_t)p * DM * DI); tt.dst[16 + p] = (u64)(W1T + (size_t)p * DI * DM);
            tt.src[20 + p] = (u64)(W2 + (size_t)p * DI * DM); tt.dst[20 + p] = (u64)(W2T + (size_t)p * DM * DI);
        }
        transpose_all_kernel<<<12288, dim3(32, 8)>>>(tt);
    }

    const int MT = (NTOK + 127) / 128;    // 105
    const size_t SL = (size_t)NTOK * DM;
    const int perm[4] = {0, 2, 1, 3};     // enc -> param layer
    ulong4 nullq; nullq.x = nullq.y = nullq.z = nullq.w = 0;

    // --- QKV fused GEMMs ---
    {
        ulong4 Aq = U4(VISB, TXTB, VISB, TXTB);
        ulong4 Bq = U4(WqT4, WqT4 + (size_t)NQ * DM, nullptr, nullptr);
        ulong4 bq_ = U4(BQ4, BQ4 + NQ, nullptr, nullptr);
        gemm_bf16_k<false, false, true, false><<<dim3(NQ / 256, MT, 2), 256, GEMM_SMEM>>>(
            Aq, Bq, bq_, nullq, Q4, (size_t)NTOK * NQ, nullptr, 0, NTOK, DM, NQ);

        ulong4 Bkv = U4(WkvT4, WkvT4 + (size_t)NKV * DM, nullptr, nullptr);
        ulong4 bkv_ = U4(BKV4, BKV4 + NKV, nullptr, nullptr);
        gemm_bf16_k<false, false, true, false><<<dim3(NKV / 256, MT, 2), 256, GEMM_SMEM>>>(
            Aq, Bkv, bkv_, nullq, KV4, (size_t)NTOK * NKV, nullptr, 0, NTOK, DM, NKV);
    }

    // --- attention ---
    attn_kernel<<<dim3(BATCH, NH, 4), 96>>>();

    // --- proj + residual ---
    {
        const size_t BLK = (size_t)DM * DM;
        ulong4 Aq = U4(CTXB4, CTXB4 + SL, CTXB4 + 2 * SL, CTXB4 + 3 * SL);
        ulong4 Bq = U4(WoT + perm[0] * BLK, WoT + perm[1] * BLK, WoT + perm[2] * BLK, WoT + perm[3] * BLK);
        ulong4 bq_ = U4(bo + perm[0] * DM, bo + perm[1] * DM, bo + perm[2] * DM, bo + perm[3] * DM);
        ulong4 Rq = U4(vis, vis, txt, txt);
        gemm_bf16_k<false, true, true, false><<<dim3(DM / 256, MT, 4), 256, GEMM_SMEM>>>(
            Aq, Bq, bq_, Rq, T14, SL, nullptr, 0, NTOK, DM, DM);
    }
    // --- LN1 ---
    {
        ulong4 gq = U4(g1 + perm[0] * DM, g1 + perm[1] * DM, g1 + perm[2] * DM, g1 + perm[3] * DM);
        ulong4 bq_ = U4(be1 + perm[0] * DM, be1 + perm[1] * DM, be1 + perm[2] * DM, be1 + perm[3] * DM);
        ln1_kernel<<<dim3(NTOK, 4), 128>>>(T14, SL, gq, bq_, OUT14, SL, OUT1B4, SL);
    }
    // --- FFN1 (relu, bf16 out) ---
    {
        ulong4 Aq = U4(OUT1B4, OUT1B4 + SL, OUT1B4 + 2 * SL, OUT1B4 + 3 * SL);
        const size_t WB = (size_t)DI * DM;
        ulong4 Bq = U4(W1T + perm[0] * WB, W1T + perm[1] * WB, W1T + perm[2] * WB, W1T + perm[3] * WB);
        ulong4 bq_ = U4(b1 + perm[0] * DI, b1 + perm[1] * DI, b1 + perm[2] * DI, b1 + perm[3] * DI);
        gemm_bf16_k<true, false, false, true><<<dim3(DI / 256, MT, 4), 256, GEMM_SMEM>>>(
            Aq, Bq, bq_, nullq, nullptr, 0, HB4, (size_t)NTOK * DI, NTOK, DM, DI);
    }
    // --- FFN2 + residual out1 ---
    {
        const size_t HL = (size_t)NTOK * DI;
        ulong4 Aq = U4(HB4, HB4 + HL, HB4 + 2 * HL, HB4 + 3 * HL);
        const size_t WB = (size_t)DM * DI;
        ulong4 Bq = U4(W2T + perm[0] * WB, W2T + perm[1] * WB, W2T + perm[2] * WB, W2T + perm[3] * WB);
        ulong4 bq_ = U4(b2 + perm[0] * DM, b2 + perm[1] * DM, b2 + perm[2] * DM, b2 + perm[3] * DM);
        ulong4 Rq = U4(OUT14, OUT14 + SL, OUT14 + 2 * SL, OUT14 + 3 * SL);
        gemm_bf16_k<false, true, true, false><<<dim3(DM / 256, MT, 4), 256, GEMM_SMEM>>>(
            Aq, Bq, bq_, Rq, T14, SL, nullptr, 0, NTOK, DI, DM);
    }
    // --- LN2 + sum -> d_out ---
    {
        ulong4 gq = U4(g2 + perm[0] * DM, g2 + perm[1] * DM, g2 + perm[2] * DM, g2 + perm[3] * DM);
        ulong4 bq_ = U4(be2 + perm[0] * DM, be2 + perm[1] * DM, be2 + perm[2] * DM, be2 + perm[3] * DM);
        ln2_pair_kernel<<<dim3(NTOK, 2), 128>>>(T14, SL, gq, bq_, out);
    }
}

// round 8
// speedup vs baseline: 1.2214x; 1.2214x over previous
#include <cuda_runtime.h>
#include <cuda_bf16.h>
#include <math.h>
#include <stdint.h>

#define NTOK 13320
#define BATCH 240
#define DM 512
#define DI 2048
#define NH 8
#define DKH 64
#define LNEPS 1e-5f
#define NQ 1024
#define NKV 2048

typedef unsigned long long u64;

// ================= scratch (static device globals; no allocation) =================
__device__ float g_Q4 [2 * NTOK * NQ];
__device__ float g_KV4[2 * NTOK * NKV];
__device__ float g_t14  [4 * NTOK * DM];
__device__ float g_out14[4 * NTOK * DM];
__device__ int   g_offs[BATCH + 1];
__device__ float g_bq4 [2 * NQ];
__device__ float g_bkv4[2 * NKV];

__device__ __nv_bfloat16 g_visb  [NTOK * DM];
__device__ __nv_bfloat16 g_txtb  [NTOK * DM];
__device__ __nv_bfloat16 g_ctxb4 [4 * NTOK * DM];
__device__ __nv_bfloat16 g_out1b4[4 * NTOK * DM];
__device__ __nv_bfloat16 g_hb4   [4 * NTOK * DI];

__device__ __nv_bfloat16 g_WqT4 [2 * NQ * DM];
__device__ __nv_bfloat16 g_WkvT4[2 * NKV * DM];
__device__ __nv_bfloat16 g_WoT  [4 * DM * DM];
__device__ __nv_bfloat16 g_W1T  [4 * DI * DM];
__device__ __nv_bfloat16 g_W2T  [4 * DM * DI];

// ================= helpers =================
__device__ __forceinline__ uint32_t smem_u32(const void* p) {
    uint32_t a;
    asm("{ .reg .u64 t; cvta.to.shared.u64 t, %1; cvt.u32.u64 %0, t; }" : "=r"(a) : "l"(p));
    return a;
}
__device__ __forceinline__ void cp_async16(uint32_t dst, const void* src) {
    asm volatile("cp.async.cg.shared.global [%0], [%1], 16;" :: "r"(dst), "l"(src));
}
#define CP_COMMIT() asm volatile("cp.async.commit_group;" ::: "memory")
#define CP_WAIT(n)  asm volatile("cp.async.wait_group %0;" :: "n"(n) : "memory")

__device__ __forceinline__ void ldmatrix_x4(uint32_t& r0, uint32_t& r1, uint32_t& r2, uint32_t& r3, uint32_t addr) {
    asm volatile("ldmatrix.sync.aligned.m8n8.x4.shared.b16 {%0,%1,%2,%3}, [%4];"
        : "=r"(r0), "=r"(r1), "=r"(r2), "=r"(r3) : "r"(addr));
}
__device__ __forceinline__ void mma_bf16(float* d, const uint32_t* a, const uint32_t* b) {
    asm volatile("mma.sync.aligned.m16n8k16.row.col.f32.bf16.bf16.f32 "
        "{%0,%1,%2,%3}, {%4,%5,%6,%7}, {%8,%9}, {%0,%1,%2,%3};"
        : "+f"(d[0]), "+f"(d[1]), "+f"(d[2]), "+f"(d[3])
        : "r"(a[0]), "r"(a[1]), "r"(a[2]), "r"(a[3]), "r"(b[0]), "r"(b[1]));
}
__device__ __forceinline__ u64 q_at(const ulong4& q, int z) {
    u64 v;
    switch (z) { case 0: v = q.x; break; case 1: v = q.y; break;
                 case 2: v = q.z; break; default: v = q.w; }
    return v;
}

// ================= prepass kernels =================
__global__ void offsets_kernel(const int* __restrict__ num_objs) {
    if (threadIdx.x == 0) {
        int s = 0;
        for (int i = 0; i < BATCH; i++) { g_offs[i] = s; s += num_objs[i]; }
        g_offs[BATCH] = s;
    }
}

__global__ void bias_concat_kernel(const float* __restrict__ bq, const float* __restrict__ bk,
                                   const float* __restrict__ bv) {
    int i = blockIdx.x * blockDim.x + threadIdx.x;
    if (i < 2 * NQ) {
        int src = i >> 10, half = (i >> 9) & 1, j = i & 511;
        int p = src + 2 * half;
        g_bq4[i] = bq[p * DM + j];
    } else if (i < 2 * NQ + 2 * NKV) {
        int k = i - 2 * NQ;
        int src = k >> 11, r = k & 2047;
        int half = r >> 10, part = (r >> 9) & 1, j = r & 511;
        const int pt[2][2] = { {0, 3}, {2, 1} };
        int p = pt[src][half];
        g_bkv4[k] = (part ? bv : bk)[p * DM + j];
    }
}

__global__ __launch_bounds__(256) void cvt_bf16_kernel(const float* __restrict__ V,
                                                       const float* __restrict__ T, int n4) {
    int i = blockIdx.x * blockDim.x + threadIdx.x;
    const float* X; __nv_bfloat16* Y; int j;
    if (i < n4) { X = V; Y = g_visb; j = i; }
    else if (i < 2 * n4) { X = T; Y = g_txtb; j = i - n4; }
    else return;
    float4 v = ((const float4*)X)[j];
    __nv_bfloat162 a, b;
    a.x = __float2bfloat16_rn(v.x); a.y = __float2bfloat16_rn(v.y);
    b.x = __float2bfloat16_rn(v.z); b.y = __float2bfloat16_rn(v.w);
    ((__nv_bfloat162*)Y)[j * 2 + 0] = a;
    ((__nv_bfloat162*)Y)[j * 2 + 1] = b;
}

struct TT { u64 src[24]; u64 dst[24]; };
__global__ __launch_bounds__(256) void transpose_all_kernel(TT tt) {
    int bid = blockIdx.x;
    int e, t, R, C;
    if (bid < 4096)      { e = bid >> 8, t = bid & 255;  R = 512;  C = 512;  }
    else if (bid < 8192) { e = 16 + ((bid - 4096) >> 10); t = (bid - 4096) & 1023; R = 512;  C = 2048; }
    else                 { e = 20 + ((bid - 8192) >> 10); t = (bid - 8192) & 1023; R = 2048; C = 512;  }
    const float* Sp = (const float*)tt.src[e];
    __nv_bfloat16* Dp = (__nv_bfloat16*)tt.dst[e];
    int tpr = C >> 5;
    int bx = (t % tpr) * 32, by = (t / tpr) * 32;

    __shared__ float tile[32][33];
    int x = bx + threadIdx.x;
#pragma unroll
    for (int yy = threadIdx.y; yy < 32; yy += 8)
        tile[yy][threadIdx.x] = Sp[(size_t)(by + yy) * C + x];
    __syncthreads();
    int x2 = by + threadIdx.x;
#pragma unroll
    for (int yy = threadIdx.y; yy < 32; yy += 8)
        Dp[(size_t)(bx + yy) * R + x2] = __float2bfloat16_rn(tile[threadIdx.x][yy]);
}

// ======== bf16 mma.sync GEMM, 128x128 tile, BK=64, 3-stage, z-batched ========
#define LDSH 72                            // 64 halves + 8 pad
#define TILEB (128 * LDSH * 2)             // 18432
#define STAGEB (2 * TILEB)                 // 36864
#define NSTAGE 3
#define GEMM_SMEM (NSTAGE * STAGEB)        // 110592

template <bool RELU, bool RESID, bool OF32, bool OBF16>
__global__ __launch_bounds__(256, 2) void gemm_bf16_k(
    ulong4 Aq, ulong4 Btq, ulong4 biasq, ulong4 Rq,
    float* __restrict__ C, size_t cStr, __nv_bfloat16* __restrict__ Cb, size_t cbStr,
    int M, int K, int N)
{
    extern __shared__ char smem[];
    const uint32_t sb = smem_u32(smem);
    const int tid = threadIdx.x;
    const int lane = tid & 31;
    const int wid = tid >> 5;
    const int z = blockIdx.z;
    const int m0 = blockIdx.y * 128;
    const int n0 = blockIdx.x * 128;
    const int warp_m = wid & 1;          // 2 -> 64-row bands
    const int warp_n = wid >> 1;         // 4 -> 32-col bands

    const __nv_bfloat16* A  = (const __nv_bfloat16*)q_at(Aq, z);
    const __nv_bfloat16* Bt = (const __nv_bfloat16*)q_at(Btq, z);
    const float* bias = (const float*)q_at(biasq, z);
    const float* R = RESID ? (const float*)q_at(Rq, z) : nullptr;
    if (OF32)  C  += (size_t)z * cStr;
    if (OBF16) Cb += (size_t)z * cbStr;

    float acc[4][4][4];
#pragma unroll
    for (int i = 0; i < 4; i++)
#pragma unroll
        for (int j = 0; j < 4; j++)
#pragma unroll
            for (int r = 0; r < 4; r++) acc[i][j][r] = 0.f;

    const int lmrow  = lane & 15;
    const int lmbyte = (lane >> 4) * 16;
    const int KT = K >> 6;               // BK=64

    auto load_stage = [&](int s, int kit) {
        const int k0 = kit << 6;
        const uint32_t base = sb + (uint32_t)s * STAGEB;
#pragma unroll
        for (int i = 0; i < 4; i++) {
            int c = tid + i * 256;            // 0..1023
            int row = c >> 3, c16 = c & 7;
            int gr = m0 + row; gr = gr < M ? gr : M - 1;
            cp_async16(base + row * (LDSH * 2) + c16 * 16,
                       A + (size_t)gr * K + k0 + c16 * 8);
        }
#pragma unroll
        for (int i = 0; i < 4; i++) {
            int c = tid + i * 256;
            int row = c >> 3, c16 = c & 7;
            cp_async16(base + TILEB + row * (LDSH * 2) + c16 * 16,
                       Bt + (size_t)(n0 + row) * K + k0 + c16 * 8);
        }
        CP_COMMIT();
    };

#pragma unroll
    for (int s = 0; s < NSTAGE - 1; s++) load_stage(s, s);

#pragma unroll 1
    for (int it = 0; it < KT; it++) {
        CP_WAIT(NSTAGE - 2);
        __syncthreads();                       // all warps done reading stage (it-1)%3
        int nk = it + NSTAGE - 1;
        if (nk < KT) load_stage(nk % NSTAGE, nk);  // overwrites stage (it-1)%3: safe
        else CP_COMMIT();

        const uint32_t ab = sb + (uint32_t)(it % NSTAGE) * STAGEB;
        const uint32_t bb = ab + TILEB;

#pragma unroll
        for (int kk = 0; kk < 4; kk++) {
            uint32_t af[4][4];
#pragma unroll
            for (int mi = 0; mi < 4; mi++) {
                uint32_t addr = ab + (warp_m * 64 + mi * 16 + lmrow) * (LDSH * 2) + kk * 32 + lmbyte;
                ldmatrix_x4(af[mi][0], af[mi][1], af[mi][2], af[mi][3], addr);
            }
            uint32_t bf[4][2];
#pragma unroll
            for (int t = 0; t < 2; t++) {
                uint32_t addr = bb + (warp_n * 32 + t * 16 + lmrow) * (LDSH * 2) + kk * 32 + lmbyte;
                uint32_t r0, r1, r2, r3;
                ldmatrix_x4(r0, r1, r2, r3, addr);
                bf[t * 2 + 0][0] = r0; bf[t * 2 + 0][1] = r2;
                bf[t * 2 + 1][0] = r1; bf[t * 2 + 1][1] = r3;
            }
#pragma unroll
            for (int mi = 0; mi < 4; mi++)
#pragma unroll
                for (int nj = 0; nj < 4; nj++)
                    mma_bf16(acc[mi][nj], af[mi], bf[nj]);
        }
    }

    const int er = lane >> 2;
    const int ec = (lane & 3) * 2;
#pragma unroll
    for (int mi = 0; mi < 4; mi++) {
#pragma unroll
        for (int half = 0; half < 2; half++) {
            int row = m0 + warp_m * 64 + mi * 16 + half * 8 + er;
            if (row >= M) continue;
#pragma unroll
            for (int nj = 0; nj < 4; nj++) {
                int col = n0 + warp_n * 32 + nj * 8 + ec;
                float2 v;
                v.x = acc[mi][nj][half * 2 + 0] + bias[col + 0];
                v.y = acc[mi][nj][half * 2 + 1] + bias[col + 1];
                if (RESID) {
                    const float2 rv = *(const float2*)(R + (size_t)row * N + col);
                    v.x += rv.x; v.y += rv.y;
                }
                if (RELU) { v.x = fmaxf(v.x, 0.f); v.y = fmaxf(v.y, 0.f); }
                if (OF32)
                    *(float2*)(C + (size_t)row * N + col) = v;
                if (OBF16) {
                    __nv_bfloat162 h2;
                    h2.x = __float2bfloat16_rn(v.x);
                    h2.y = __float2bfloat16_rn(v.y);
                    *(__nv_bfloat162*)(Cb + (size_t)row * N + col) = h2;
                }
            }
        }
    }
}

// ================= LN1 (z-batched, f32 + bf16 out) =================
__global__ __launch_bounds__(128) void ln1_kernel(
    const float* __restrict__ X, size_t xStr, ulong4 gq, ulong4 bq,
    float* __restrict__ out, size_t oStr, __nv_bfloat16* __restrict__ outb, size_t obStr)
{
    int row = blockIdx.x;
    int e = blockIdx.y;
    int tid = threadIdx.x;
    X += (size_t)e * xStr;
    out += (size_t)e * oStr;
    const float* g = (const float*)q_at(gq, e);
    const float* b = (const float*)q_at(bq, e);

    float4 v = ((const float4*)(X + (size_t)row * DM))[tid];
    __shared__ float sbuf[8];
    int wid = tid >> 5, lane = tid & 31;

    float s = v.x + v.y + v.z + v.w;
#pragma unroll
    for (int o = 16; o > 0; o >>= 1) s += __shfl_xor_sync(0xffffffffu, s, o);
    if (lane == 0) sbuf[wid] = s;
    __syncthreads();
    float mean = (sbuf[0] + sbuf[1] + sbuf[2] + sbuf[3]) * (1.0f / DM);
    __syncthreads();

    float dx0 = v.x - mean, dx1 = v.y - mean, dx2 = v.z - mean, dx3 = v.w - mean;
    float sq = dx0 * dx0 + dx1 * dx1 + dx2 * dx2 + dx3 * dx3;
#pragma unroll
    for (int o = 16; o > 0; o >>= 1) sq += __shfl_xor_sync(0xffffffffu, sq, o);
    if (lane == 0) sbuf[wid] = sq;
    __syncthreads();
    float var = (sbuf[0] + sbuf[1] + sbuf[2] + sbuf[3]) * (1.0f / DM);
    float rstd = rsqrtf(var + LNEPS);

    float4 gg = ((const float4*)g)[tid];
    float4 bb = ((const float4*)b)[tid];
    float4 y;
    y.x = dx0 * rstd * gg.x + bb.x;
    y.y = dx1 * rstd * gg.y + bb.y;
    y.z = dx2 * rstd * gg.z + bb.z;
    y.w = dx3 * rstd * gg.w + bb.w;

    ((float4*)(out + (size_t)row * DM))[tid] = y;
    __nv_bfloat16* ob = outb + (size_t)e * obStr + (size_t)row * DM;
    __nv_bfloat162 a, c;
    a.x = __float2bfloat16_rn(y.x); a.y = __float2bfloat16_rn(y.y);
    c.x = __float2bfloat16_rn(y.z); c.y = __float2bfloat16_rn(y.w);
    ((__nv_bfloat162*)ob)[tid * 2 + 0] = a;
    ((__nv_bfloat162*)ob)[tid * 2 + 1] = c;
}

// ============ LN2 pair + sum: out[p] = LN(T14[2p]) + LN(T14[2p+1]) ============
__global__ __launch_bounds__(128) void ln2_pair_kernel(
    const float* __restrict__ X, size_t xStr, ulong4 gq, ulong4 bq, float* __restrict__ out)
{
    int row = blockIdx.x;
    int p = blockIdx.y;
    int tid = threadIdx.x;
    int wid = tid >> 5, lane = tid & 31;

    const float* X0 = X + (size_t)(2 * p) * xStr + (size_t)row * DM;
    const float* X1 = X + (size_t)(2 * p + 1) * xStr + (size_t)row * DM;
    float4 v0 = ((const float4*)X0)[tid];
    float4 v1 = ((const float4*)X1)[tid];

    __shared__ float sbuf[16];
    float s0 = v0.x + v0.y + v0.z + v0.w;
    float s1 = v1.x + v1.y + v1.z + v1.w;
#pragma unroll
    for (int o = 16; o > 0; o >>= 1) {
        s0 += __shfl_xor_sync(0xffffffffu, s0, o);
        s1 += __shfl_xor_sync(0xffffffffu, s1, o);
    }
    if (lane == 0) { sbuf[wid] = s0; sbuf[8 + wid] = s1; }
    __syncthreads();
    float mean0 = (sbuf[0] + sbuf[1] + sbuf[2] + sbuf[3]) * (1.0f / DM);
    float mean1 = (sbuf[8] + sbuf[9] + sbuf[10] + sbuf[11]) * (1.0f / DM);
    __syncthreads();

    float a0 = v0.x - mean0, a1 = v0.y - mean0, a2 = v0.z - mean0, a3 = v0.w - mean0;
    float c0 = v1.x - mean1, c1 = v1.y - mean1, c2 = v1.z - mean1, c3 = v1.w - mean1;
    float q0 = a0 * a0 + a1 * a1 + a2 * a2 + a3 * a3;
    float q1 = c0 * c0 + c1 * c1 + c2 * c2 + c3 * c3;
#pragma unroll
    for (int o = 16; o > 0; o >>= 1) {
        q0 += __shfl_xor_sync(0xffffffffu, q0, o);
        q1 += __shfl_xor_sync(0xffffffffu, q1, o);
    }
    if (lane == 0) { sbuf[wid] = q0; sbuf[8 + wid] = q1; }
    __syncthreads();
    float rstd0 = rsqrtf((sbuf[0] + sbuf[1] + sbuf[2] + sbuf[3]) * (1.0f / DM) + LNEPS);
    float rstd1 = rsqrtf((sbuf[8] + sbuf[9] + sbuf[10] + sbuf[11]) * (1.0f / DM) + LNEPS);

    const float* g0 = (const float*)q_at(gq, 2 * p);
    const float* b0 = (const float*)q_at(bq, 2 * p);
    const float* g1 = (const float*)q_at(gq, 2 * p + 1);
    const float* b1 = (const float*)q_at(bq, 2 * p + 1);
    float4 gg0 = ((const float4*)g0)[tid], bb0 = ((const float4*)b0)[tid];
    float4 gg1 = ((const float4*)g1)[tid], bb1 = ((const float4*)b1)[tid];

    float4 y;
    y.x = (a0 * rstd0 * gg0.x + bb0.x) + (c0 * rstd1 * gg1.x + bb1.x);
    y.y = (a1 * rstd0 * gg0.y + bb0.y) + (c1 * rstd1 * gg1.y + bb1.y);
    y.z = (a2 * rstd0 * gg0.z + bb0.z) + (c2 * rstd1 * gg1.z + bb1.z);
    y.w = (a3 * rstd0 * gg0.w + bb0.w) + (c3 * rstd1 * gg1.w + bb1.w);

    ((float4*)(out + (size_t)p * NTOK * DM + (size_t)row * DM))[tid] = y;
}

// ================= segment attention (all 4 encoders) =================
__global__ __launch_bounds__(96) void attn_kernel()
{
    int s = blockIdx.x;
    int h = blockIdx.y;
    int e = blockIdx.z;
    int off = g_offs[s];
    int L = g_offs[s + 1] - off;

    const int srcQ = e >> 1, halfQ = e & 1;
    const int srcKV_t[4]  = {0, 1, 1, 0};
    const int halfKV_t[4] = {0, 0, 1, 1};
    const int srcKV = srcKV_t[e], halfKV = halfKV_t[e];

    const float* Qbase = g_Q4  + (size_t)srcQ  * NTOK * NQ  + halfQ  * DM + h * DKH;
    const float* Kbase = g_KV4 + (size_t)srcKV * NTOK * NKV + halfKV * NQ + h * DKH;
    const float* Vbase = Kbase + DM;

    __shared__ float Ks[95 * DKH];
    __shared__ float Vs[95 * DKH];
    for (int idx = threadIdx.x; idx < L * 16; idx += 96) {
        int j = idx >> 4, d4 = idx & 15;
        ((float4*)Ks)[j * 16 + d4] = ((const float4*)(Kbase + (size_t)(off + j) * NKV))[d4];
        ((float4*)Vs)[j * 16 + d4] = ((const float4*)(Vbase + (size_t)(off + j) * NKV))[d4];
    }
    __syncthreads();

    int i = threadIdx.x;
    if (i >= L) return;

    float q[DKH];
    const float4* qp = (const float4*)(Qbase + (size_t)(off + i) * NQ);
#pragma unroll
    for (int t = 0; t < 16; t++) {
        float4 u = qp[t];
        q[4 * t + 0] = u.x; q[4 * t + 1] = u.y; q[4 * t + 2] = u.z; q[4 * t + 3] = u.w;
    }

    float m = -INFINITY, l = 0.f;
    float acc[DKH];
#pragma unroll
    for (int d = 0; d < DKH; d++) acc[d] = 0.f;

    for (int j0 = 0; j0 < L; j0 += 8) {
        int nj = L - j0; if (nj > 8) nj = 8;
        float sc[8];
#pragma unroll
        for (int jj = 0; jj < 8; jj++) {
            if (jj < nj) {
                const float4* kr = (const float4*)&Ks[(j0 + jj) * DKH];
                float sd = 0.f;
#pragma unroll
                for (int t = 0; t < 16; t++) {
                    float4 kv = kr[t];
                    sd = fmaf(q[4 * t + 0], kv.x, sd);
                    sd = fmaf(q[4 * t + 1], kv.y, sd);
                    sd = fmaf(q[4 * t + 2], kv.z, sd);
                    sd = fmaf(q[4 * t + 3], kv.w, sd);
                }
                sc[jj] = sd * 0.125f;
            } else sc[jj] = -INFINITY;
        }
        float cm = sc[0];
#pragma unroll
        for (int jj = 1; jj < 8; jj++) cm = fmaxf(cm, sc[jj]);
        float mn = fmaxf(m, cm);
        float corr = __expf(m - mn);
        l *= corr;
#pragma unroll
        for (int d = 0; d < DKH; d++) acc[d] *= corr;
#pragma unroll
        for (int jj = 0; jj < 8; jj++) {
            if (jj < nj) {
                float p = __expf(sc[jj] - mn);
                l += p;
                const float4* vr = (const float4*)&Vs[(j0 + jj) * DKH];
#pragma unroll
                for (int t = 0; t < 16; t++) {
                    float4 vv = vr[t];
                    acc[4 * t + 0] = fmaf(p, vv.x, acc[4 * t + 0]);
                    acc[4 * t + 1] = fmaf(p, vv.y, acc[4 * t + 1]);
                    acc[4 * t + 2] = fmaf(p, vv.z, acc[4 * t + 2]);
                    acc[4 * t + 3] = fmaf(p, vv.w, acc[4 * t + 3]);
                }
            }
        }
        m = mn;
    }

    float inv = 1.0f / l;
    __nv_bfloat162* o = (__nv_bfloat162*)(g_ctxb4 + (size_t)e * NTOK * DM + (size_t)(off + i) * DM + h * DKH);
#pragma unroll
    for (int t = 0; t < 32; t++) {
        __nv_bfloat162 h2;
        h2.x = __float2bfloat16_rn(acc[2 * t + 0] * inv);
        h2.y = __float2bfloat16_rn(acc[2 * t + 1] * inv);
        o[t] = h2;
    }
}

// ================= host =================
extern "C" void kernel_launch(void* const* d_in, const int* in_sizes, int n_in,
                              void* d_out, int out_size)
{
    const float* vis  = (const float*)d_in[0];
    const float* txt  = (const float*)d_in[1];
    const float* Wq   = (const float*)d_in[2];
    const float* bq   = (const float*)d_in[3];
    const float* Wk   = (const float*)d_in[4];
    const float* bk   = (const float*)d_in[5];
    const float* Wv   = (const float*)d_in[6];
    const float* bv   = (const float*)d_in[7];
    const float* Wo   = (const float*)d_in[8];
    const float* bo   = (const float*)d_in[9];
    const float* g1   = (const float*)d_in[10];
    const float* be1  = (const float*)d_in[11];
    const float* W1   = (const float*)d_in[12];
    const float* b1   = (const float*)d_in[13];
    const float* W2   = (const float*)d_in[14];
    const float* b2   = (const float*)d_in[15];
    const float* g2   = (const float*)d_in[16];
    const float* be2  = (const float*)d_in[17];
    const int*   nobj = (const int*)d_in[18];
    float* out = (float*)d_out;

    float *Q4, *KV4, *T14, *OUT14, *BQ4, *BKV4;
    __nv_bfloat16 *VISB, *TXTB, *CTXB4, *OUT1B4, *HB4;
    __nv_bfloat16 *WqT4, *WkvT4, *WoT, *W1T, *W2T;
    cudaGetSymbolAddress((void**)&Q4, g_Q4);
    cudaGetSymbolAddress((void**)&KV4, g_KV4);
    cudaGetSymbolAddress((void**)&T14, g_t14);
    cudaGetSymbolAddress((void**)&OUT14, g_out14);
    cudaGetSymbolAddress((void**)&BQ4, g_bq4);
    cudaGetSymbolAddress((void**)&BKV4, g_bkv4);
    cudaGetSymbolAddress((void**)&VISB, g_visb);
    cudaGetSymbolAddress((void**)&TXTB, g_txtb);
    cudaGetSymbolAddress((void**)&CTXB4, g_ctxb4);
    cudaGetSymbolAddress((void**)&OUT1B4, g_out1b4);
    cudaGetSymbolAddress((void**)&HB4, g_hb4);
    cudaGetSymbolAddress((void**)&WqT4, g_WqT4);
    cudaGetSymbolAddress((void**)&WkvT4, g_WkvT4);
    cudaGetSymbolAddress((void**)&WoT, g_WoT);
    cudaGetSymbolAddress((void**)&W1T, g_W1T);
    cudaGetSymbolAddress((void**)&W2T, g_W2T);

    cudaFuncSetAttribute(gemm_bf16_k<false, false, true,  false>, cudaFuncAttributeMaxDynamicSharedMemorySize, GEMM_SMEM);
    cudaFuncSetAttribute(gemm_bf16_k<false, true,  true,  false>, cudaFuncAttributeMaxDynamicSharedMemorySize, GEMM_SMEM);
    cudaFuncSetAttribute(gemm_bf16_k<true,  false, false, true >, cudaFuncAttributeMaxDynamicSharedMemorySize, GEMM_SMEM);

    auto U4 = [](const void* a, const void* b, const void* c, const void* d) {
        ulong4 u; u.x = (u64)a; u.y = (u64)b; u.z = (u64)c; u.w = (u64)d; return u;
    };

    offsets_kernel<<<1, 32>>>(nobj);
    bias_concat_kernel<<<24, 256>>>(bq, bk, bv);

    const int NC4 = NTOK * DM / 4;
    cvt_bf16_kernel<<<(2 * NC4 + 255) / 256, 256>>>(vis, txt, NC4);

    {
        TT tt;
        const size_t BLK = (size_t)DM * DM;
        const u64 qoff[4] = {0, 2 * BLK, BLK, 3 * BLK};
        const u64 koff[4] = {0, 6 * BLK, 4 * BLK, 2 * BLK};
        const u64 voff[4] = {BLK, 7 * BLK, 5 * BLK, 3 * BLK};
        for (int p = 0; p < 4; p++) {
            tt.src[p]      = (u64)(Wq + (size_t)p * BLK); tt.dst[p]      = (u64)(WqT4 + qoff[p]);
            tt.src[4 + p]  = (u64)(Wk + (size_t)p * BLK); tt.dst[4 + p]  = (u64)(WkvT4 + koff[p]);
            tt.src[8 + p]  = (u64)(Wv + (size_t)p * BLK); tt.dst[8 + p]  = (u64)(WkvT4 + voff[p]);
            tt.src[12 + p] = (u64)(Wo + (size_t)p * BLK); tt.dst[12 + p] = (u64)(WoT + (size_t)p * BLK);
            tt.src[16 + p] = (u64)(W1 + (size_t)p * DM * DI); tt.dst[16 + p] = (u64)(W1T + (size_t)p * DI * DM);
            tt.src[20 + p] = (u64)(W2 + (size_t)p * DI * DM); tt.dst[20 + p] = (u64)(W2T + (size_t)p * DM * DI);
        }
        transpose_all_kernel<<<12288, dim3(32, 8)>>>(tt);
    }

    const int MT = (NTOK + 127) / 128;    // 105
    const size_t SL = (size_t)NTOK * DM;
    const int perm[4] = {0, 2, 1, 3};
    ulong4 nullq; nullq.x = nullq.y = nullq.z = nullq.w = 0;

    // --- QKV fused GEMMs ---
    {
        ulong4 Aq = U4(VISB, TXTB, VISB, TXTB);
        ulong4 Bq = U4(WqT4, WqT4 + (size_t)NQ * DM, nullptr, nullptr);
        ulong4 bq_ = U4(BQ4, BQ4 + NQ, nullptr, nullptr);
        gemm_bf16_k<false, false, true, false><<<dim3(NQ / 128, MT, 2), 256, GEMM_SMEM>>>(
            Aq, Bq, bq_, nullq, Q4, (size_t)NTOK * NQ, nullptr, 0, NTOK, DM, NQ);

        ulong4 Bkv = U4(WkvT4, WkvT4 + (size_t)NKV * DM, nullptr, nullptr);
        ulong4 bkv_ = U4(BKV4, BKV4 + NKV, nullptr, nullptr);
        gemm_bf16_k<false, false, true, false><<<dim3(NKV / 128, MT, 2), 256, GEMM_SMEM>>>(
            Aq, Bkv, bkv_, nullq, KV4, (size_t)NTOK * NKV, nullptr, 0, NTOK, DM, NKV);
    }

    // --- attention ---
    attn_kernel<<<dim3(BATCH, NH, 4), 96>>>();

    // --- proj + residual ---
    {
        const size_t BLK = (size_t)DM * DM;
        ulong4 Aq = U4(CTXB4, CTXB4 + SL, CTXB4 + 2 * SL, CTXB4 + 3 * SL);
        ulong4 Bq = U4(WoT + perm[0] * BLK, WoT + perm[1] * BLK, WoT + perm[2] * BLK, WoT + perm[3] * BLK);
        ulong4 bq_ = U4(bo + perm[0] * DM, bo + perm[1] * DM, bo + perm[2] * DM, bo + perm[3] * DM);
        ulong4 Rq = U4(vis, vis, txt, txt);
        gemm_bf16_k<false, true, true, false><<<dim3(DM / 128, MT, 4), 256, GEMM_SMEM>>>(
            Aq, Bq, bq_, Rq, T14, SL, nullptr, 0, NTOK, DM, DM);
    }
    // --- LN1 ---
    {
        ulong4 gq = U4(g1 + perm[0] * DM, g1 + perm[1] * DM, g1 + perm[2] * DM, g1 + perm[3] * DM);
        ulong4 bq_ = U4(be1 + perm[0] * DM, be1 + perm[1] * DM, be1 + perm[2] * DM, be1 + perm[3] * DM);
        ln1_kernel<<<dim3(NTOK, 4), 128>>>(T14, SL, gq, bq_, OUT14, SL, OUT1B4, SL);
    }
    // --- FFN1 ---
    {
        ulong4 Aq = U4(OUT1B4, OUT1B4 + SL, OUT1B4 + 2 * SL, OUT1B4 + 3 * SL);
        const size_t WB = (size_t)DI * DM;
        ulong4 Bq = U4(W1T + perm[0] * WB, W1T + perm[1] * WB, W1T + perm[2] * WB, W1T + perm[3] * WB);
        ulong4 bq_ = U4(b1 + perm[0] * DI, b1 + perm[1] * DI, b1 + perm[2] * DI, b1 + perm[3] * DI);
        gemm_bf16_k<true, false, false, true><<<dim3(DI / 128, MT, 4), 256, GEMM_SMEM>>>(
            Aq, Bq, bq_, nullq, nullptr, 0, HB4, (size_t)NTOK * DI, NTOK, DM, DI);
    }
    // --- FFN2 + residual ---
    {
        const size_t HL = (size_t)NTOK * DI;
        ulong4 Aq = U4(HB4, HB4 + HL, HB4 + 2 * HL, HB4 + 3 * HL);
        const size_t WB = (size_t)DM * DI;
        ulong4 Bq = U4(W2T + perm[0] * WB, W2T + perm[1] * WB, W2T + perm[2] * WB, W2T + perm[3] * WB);
        ulong4 bq_ = U4(b2 + perm[0] * DM, b2 + perm[1] * DM, b2 + perm[2] * DM, b2 + perm[3] * DM);
        ulong4 Rq = U4(OUT14, OUT14 + SL, OUT14 + 2 * SL, OUT14 + 3 * SL);
        gemm_bf16_k<false, true, true, false><<<dim3(DM / 128, MT, 4), 256, GEMM_SMEM>>>(
            Aq, Bq, bq_, Rq, T14, SL, nullptr, 0, NTOK, DI, DM);
    }
    // --- LN2 + sum -> d_out ---
    {
        ulong4 gq = U4(g2 + perm[0] * DM, g2 + perm[1] * DM, g2 + perm[2] * DM, g2 + perm[3] * DM);
        ulong4 bq_ = U4(be2 + perm[0] * DM, be2 + perm[1] * DM, be2 + perm[2] * DM, be2 + perm[3] * DM);
        ln2_pair_kernel<<<dim3(NTOK, 2), 128>>>(T14, SL, gq, bq_, out);
    }
}